// round 16
// baseline (speedup 1.0000x reference)
#include <cuda_runtime.h>
#include <cuda_bf16.h>
#include <math.h>
#include <float.h>
#include <stdint.h>

#define WAY 5
#define SHOT 5
#define QUERY 15
#define EMB 640
#define NMEM 100000
#define NSIM (SHOT + NMEM)   // 100005 candidates per way
#define TOPK 8
#define EPS 1e-12f
#define INV_TEMP (1.0f / 64.0f)

#define SPLITS 32            // scan splits per way in k3a
#define CHUNK ((NSIM + SPLITS - 1) / SPLITS)   // 3126

// ---- k2 TMA pipeline geometry ----
#define K2_TILE_R 16
#define K2_TILE_BYTES (K2_TILE_R * EMB * 4)     // 40960
#define K2_STAGES 4
#define K2_NTILES (NMEM / K2_TILE_R)            // 6250 exact
#define K2_GRID 148
#define K2_THREADS 512
#define K2_CENT_BYTES (WAY * EMB * 4)           // 12800
#define K2_SMEM (K2_CENT_BYTES + K2_STAGES * K2_TILE_BYTES + 64)  // 176704

// ---------------- device scratch (static, allocation-free) ----------------
__device__ __align__(16) float g_c[WAY][EMB];   // per-way centroids
__device__ float g_sim[WAY][NSIM];              // similarity vector per way
__device__ float g_pv[WAY][SPLITS][TOPK];       // partial top-k values
__device__ int   g_pi[WAY][SPLITS][TOPK];       // partial top-k indices

typedef unsigned long long ull;

__device__ __forceinline__ float warp_sum(float v) {
#pragma unroll
    for (int o = 16; o; o >>= 1) v += __shfl_xor_sync(0xffffffffu, v, o);
    return v;
}

// orderable-uint transform: key order == float order
__device__ __forceinline__ unsigned ford(float f) {
    unsigned u = __float_as_uint(f);
    return (u & 0x80000000u) ? ~u : (u | 0x80000000u);
}
__device__ __forceinline__ unsigned unford(unsigned u) {
    return (u & 0x80000000u) ? (u & 0x7fffffffu) : ~u;
}
__device__ __forceinline__ ull warp_max_u64(ull m) {
#pragma unroll
    for (int o = 16; o; o >>= 1) {
        ull t = __shfl_xor_sync(0xffffffffu, m, o);
        if (t > m) m = t;
    }
    return m;
}

// ---------------- mbarrier / TMA helpers ------------------------------------
__device__ __forceinline__ void mbar_init(uint32_t addr, uint32_t cnt) {
    asm volatile("mbarrier.init.shared.b64 [%0], %1;" :: "r"(addr), "r"(cnt) : "memory");
}
__device__ __forceinline__ void mbar_arrive(uint32_t addr) {
    asm volatile("mbarrier.arrive.shared.b64 _, [%0];" :: "r"(addr) : "memory");
}
__device__ __forceinline__ void mbar_expect_tx(uint32_t addr, uint32_t bytes) {
    asm volatile("mbarrier.arrive.expect_tx.shared.b64 _, [%0], %1;"
                 :: "r"(addr), "r"(bytes) : "memory");
}
__device__ __forceinline__ void mbar_wait(uint32_t addr, uint32_t parity) {
    uint32_t done = 0;
    while (!done) {
        asm volatile(
            "{\n\t.reg .pred p;\n\t"
            "mbarrier.try_wait.parity.acquire.cta.shared::cta.b64 p, [%1], %2, 0x989680;\n\t"
            "selp.b32 %0, 1, 0, p;\n\t}"
            : "=r"(done) : "r"(addr), "r"(parity) : "memory");
    }
}
__device__ __forceinline__ void tma_bulk_1d(uint32_t smem_dst, const void* gsrc,
                                            uint32_t bytes, uint32_t mbar) {
    asm volatile(
        "cp.async.bulk.shared::cta.global.mbarrier::complete_tx::bytes [%0], [%1], %2, [%3];"
        :: "r"(smem_dst), "l"(gsrc), "r"(bytes), "r"(mbar) : "memory");
}

// ---------------- dummy kernel (ncu launch-index alignment) -----------------
__global__ void k_dummy() {}

// ---------------- kernel 1: per-way support prep (grid = WAY) ---------------
__global__ void k1_support(const float* __restrict__ inst) {
    int w = blockIdx.x;
    int wid  = threadIdx.x >> 5;
    int lane = threadIdx.x & 31;

    __shared__ float sinv[SHOT];
    __shared__ float sc[EMB];

    if (wid < SHOT) {
        const float* row = inst + (size_t)(wid * WAY + w) * EMB;
        float ss = 0.f;
#pragma unroll
        for (int i = 0; i < 20; i++) {
            float v = row[lane + 32 * i];
            ss += v * v;
        }
        ss = warp_sum(ss);
        if (lane == 0) sinv[wid] = 1.0f / fmaxf(sqrtf(ss), EPS);
    }
    __syncthreads();

    for (int d = threadIdx.x; d < EMB; d += blockDim.x) {
        float s = 0.f;
#pragma unroll
        for (int t = 0; t < SHOT; t++)
            s += inst[(size_t)(t * WAY + w) * EMB + d] * sinv[t];
        s *= (1.0f / SHOT);
        sc[d] = s;
        g_c[w][d] = s;
    }
    __syncthreads();

    if (wid < SHOT) {
        const float* row = inst + (size_t)(wid * WAY + w) * EMB;
        float dot = 0.f;
#pragma unroll
        for (int i = 0; i < 20; i++) {
            int d = lane + 32 * i;
            dot += row[d] * sc[d];
        }
        dot = warp_sum(dot);
        if (lane == 0) g_sim[w][wid] = dot * sinv[wid];
    }
}

// ---------------- kernel 2: TMA-staged memory-bank scan ----------------------
// 148 CTAs x 512 threads. 16-row tiles staged via cp.async.bulk through a
// 4-deep mbarrier ring (160 KB in flight/SM). Warp w consumes row w from smem.
__global__ void __launch_bounds__(K2_THREADS) k2_memscan(const float* __restrict__ mem) {
    extern __shared__ __align__(16) char smem[];
    float4 (*scent)[EMB / 4] = reinterpret_cast<float4 (*)[EMB / 4]>(smem);
    char* sdata = smem + K2_CENT_BYTES;
    uint32_t bar0 = (uint32_t)__cvta_generic_to_shared(
        smem + K2_CENT_BYTES + K2_STAGES * K2_TILE_BYTES);
    // full(s) = bar0 + s*8 ; empty(s) = bar0 + 32 + s*8

    int tid = threadIdx.x, lane = tid & 31, wid = tid >> 5;

    for (int i = tid; i < WAY * EMB / 4; i += K2_THREADS)
        (&scent[0][0])[i] = ((const float4*)g_c)[i];
    if (tid == 0) {
#pragma unroll
        for (int s = 0; s < K2_STAGES; s++) {
            mbar_init(bar0 + s * 8, 1);
            mbar_init(bar0 + 32 + s * 8, K2_THREADS);
        }
    }
    __syncthreads();

    int nk = (K2_NTILES - blockIdx.x + (K2_GRID - 1)) / K2_GRID;

    // prologue: fill the ring
    if (tid == 0) {
        int np = nk < K2_STAGES ? nk : K2_STAGES;
        for (int k = 0; k < np; k++) {
            int tile = blockIdx.x + k * K2_GRID;
            uint32_t dst = (uint32_t)__cvta_generic_to_shared(sdata + k * K2_TILE_BYTES);
            mbar_expect_tx(bar0 + k * 8, K2_TILE_BYTES);
            tma_bulk_1d(dst, mem + (size_t)tile * K2_TILE_R * EMB,
                        K2_TILE_BYTES, bar0 + k * 8);
        }
    }

    for (int k = 0; k < nk; k++) {
        int s = k & (K2_STAGES - 1);
        int tile = blockIdx.x + k * K2_GRID;
        mbar_wait(bar0 + s * 8, (k >> 2) & 1);

        const float4* row = (const float4*)(sdata + s * K2_TILE_BYTES + wid * (EMB * 4));
        float a0 = 0.f, a1 = 0.f, a2 = 0.f, a3 = 0.f, a4 = 0.f, sq = 0.f;
#pragma unroll
        for (int i = 0; i < 5; i++) {
            int ci = lane + 32 * i;
            float4 x  = row[ci];
            float4 c0 = scent[0][ci], c1 = scent[1][ci], c2 = scent[2][ci],
                   c3 = scent[3][ci], c4 = scent[4][ci];
            sq += x.x * x.x  + x.y * x.y  + x.z * x.z  + x.w * x.w;
            a0 += x.x * c0.x + x.y * c0.y + x.z * c0.z + x.w * c0.w;
            a1 += x.x * c1.x + x.y * c1.y + x.z * c1.z + x.w * c1.w;
            a2 += x.x * c2.x + x.y * c2.y + x.z * c2.z + x.w * c2.w;
            a3 += x.x * c3.x + x.y * c3.y + x.z * c3.z + x.w * c3.w;
            a4 += x.x * c4.x + x.y * c4.y + x.z * c4.z + x.w * c4.w;
        }
        // smem reads for this stage are done -> release the buffer
        mbar_arrive(bar0 + 32 + s * 8);

        sq = warp_sum(sq);
        a0 = warp_sum(a0); a1 = warp_sum(a1); a2 = warp_sum(a2);
        a3 = warp_sum(a3); a4 = warp_sum(a4);
        float inv = 1.0f / fmaxf(sqrtf(sq), EPS);
        int grow = SHOT + tile * K2_TILE_R + wid;
        if (lane < WAY) {
            float a = (lane == 0) ? a0 :
                      (lane == 1) ? a1 :
                      (lane == 2) ? a2 :
                      (lane == 3) ? a3 : a4;
            g_sim[lane][grow] = a * inv;
        }

        // producer: refill this slot for iteration k + STAGES
        if (tid == 0 && k + K2_STAGES < nk) {
            mbar_wait(bar0 + 32 + s * 8, (k >> 2) & 1);   // all 512 consumed slot s
            int tile2 = blockIdx.x + (k + K2_STAGES) * K2_GRID;
            uint32_t dst = (uint32_t)__cvta_generic_to_shared(sdata + s * K2_TILE_BYTES);
            mbar_expect_tx(bar0 + s * 8, K2_TILE_BYTES);
            tma_bulk_1d(dst, mem + (size_t)tile2 * K2_TILE_R * EMB,
                        K2_TILE_BYTES, bar0 + s * 8);
        }
    }
}

// ---------------- register-resident insert (static indices only) ------------
__device__ __forceinline__ void insert8(float* bv, int* bi, float v, int i) {
    if (v > bv[TOPK - 1]) {
        float cv = v; int ci = i;
#pragma unroll
        for (int j = 0; j < TOPK; j++) {
            if (cv > bv[j]) {
                float tv = bv[j]; bv[j] = cv; cv = tv;
                int   ti = bi[j]; bi[j] = ci; ci = ti;
            }
        }
    }
}

// ---------------- kernel 3a: partial top-8 (160 blocks, warp-level merge) ---
#define K3A_THREADS 256
__global__ void k3a_topk() {
    int w = blockIdx.x / SPLITS;
    int s = blockIdx.x % SPLITS;
    int lo = s * CHUNK;
    int hi = min(lo + CHUNK, NSIM);
    const float* sim = g_sim[w];
    int tid = threadIdx.x;
    int lane = tid & 31, wid = tid >> 5;

    float bv[TOPK]; int bi[TOPK];
#pragma unroll
    for (int j = 0; j < TOPK; j++) { bv[j] = -FLT_MAX; bi[j] = 0x7fffffff; }

    int i = lo + tid;
    for (; i + 3 * K3A_THREADS < hi; i += 4 * K3A_THREADS) {
        float v0 = sim[i];
        float v1 = sim[i + K3A_THREADS];
        float v2 = sim[i + 2 * K3A_THREADS];
        float v3 = sim[i + 3 * K3A_THREADS];
        insert8(bv, bi, v0, i);
        insert8(bv, bi, v1, i + K3A_THREADS);
        insert8(bv, bi, v2, i + 2 * K3A_THREADS);
        insert8(bv, bi, v3, i + 3 * K3A_THREADS);
    }
    for (; i < hi; i += K3A_THREADS) insert8(bv, bi, sim[i], i);

    // pack to orderable u64 keys (unique: indices unique)
    ull k[TOPK];
#pragma unroll
    for (int j = 0; j < TOPK; j++)
        k[j] = ((ull)ford(bv[j]) << 32) | (unsigned)(0x7fffffff - bi[j]);

    // per-warp top-8 extraction (no smem tree)
    __shared__ ull swarp[K3A_THREADS / 32][TOPK];   // 8 warps x 8 keys
#pragma unroll
    for (int j = 0; j < TOPK; j++) {
        ull loc = k[0];
#pragma unroll
        for (int t = 1; t < TOPK; t++) loc = (k[t] > loc) ? k[t] : loc;
        ull m = warp_max_u64(loc);
#pragma unroll
        for (int t = 0; t < TOPK; t++)
            if (k[t] == m) k[t] = 0ull;
        if (lane == 0) swarp[wid][j] = m;
    }
    __syncthreads();

    // warp 0: merge 64 keys (2 per lane), extract top-8, write out
    if (wid == 0) {
        ull a = (&swarp[0][0])[lane];
        ull b = (&swarp[0][0])[lane + 32];
#pragma unroll
        for (int j = 0; j < TOPK; j++) {
            ull loc = (a > b) ? a : b;
            ull m = warp_max_u64(loc);
            if (a == m) a = 0ull;
            if (b == m) b = 0ull;
            if (lane == 0) {
                g_pv[w][s][j] = __uint_as_float(unford((unsigned)(m >> 32)));
                g_pi[w][s][j] = 0x7fffffff - (int)(unsigned)(m & 0xffffffffu);
            }
        }
    }
}

// ---------------- kernel 3b: warp-parallel merge + proto + logits -----------
// grid = WAY, 640 threads; warp 0 selects top-8 of 256 candidates
__global__ void k3b_proto_logits(const float* __restrict__ inst,
                                 const float* __restrict__ mem,
                                 float* __restrict__ out) {
    int w = blockIdx.x;
    int tid = threadIdx.x;
    int lane = tid & 31, wid = tid >> 5;

    __shared__ float cv[SPLITS * TOPK];    // 256
    __shared__ int   cx[SPLITS * TOPK];
    __shared__ float svals[TOPK];
    __shared__ int   sidx[TOPK];
    __shared__ float red[32];
    __shared__ float sp[EMB];

    if (tid < SPLITS * TOPK) {
        cv[tid] = (&g_pv[w][0][0])[tid];
        cx[tid] = (&g_pi[w][0][0])[tid];
    }
    __syncthreads();

    // warp 0: top-8 of 256 via packed u64 keys (8 per lane)
    if (wid == 0) {
        ull k[8];
#pragma unroll
        for (int t = 0; t < 8; t++) {
            float v = cv[lane + 32 * t];
            int   x = cx[lane + 32 * t];
            k[t] = ((ull)ford(v) << 32) | (unsigned)(0x7fffffff - x);
        }
#pragma unroll
        for (int j = 0; j < TOPK; j++) {
            ull loc = k[0];
#pragma unroll
            for (int t = 1; t < 8; t++) loc = (k[t] > loc) ? k[t] : loc;
            ull m = warp_max_u64(loc);
#pragma unroll
            for (int t = 0; t < 8; t++)
                if (k[t] == m) k[t] = 0ull;
            if (lane == 0) {
                svals[j] = __uint_as_float(unford((unsigned)(m >> 32)));
                sidx[j]  = 0x7fffffff - (int)(unsigned)(m & 0xffffffffu);
            }
        }
    }
    __syncthreads();

    float denom = 0.f;
#pragma unroll
    for (int j = 0; j < TOPK; j++) denom += svals[j];

    float numer = 0.f;
#pragma unroll
    for (int j = 0; j < TOPK; j++) {
        int idx = sidx[j];
        const float* src = (idx < SHOT)
            ? inst + (size_t)(idx * WAY + w) * EMB
            : mem + (size_t)(idx - SHOT) * EMB;
        numer += svals[j] * src[tid];
    }
    float p = numer / denom;

    float ss = warp_sum(p * p);
    if (lane == 0) red[wid] = ss;
    __syncthreads();
    if (wid == 0) {
        float t = (lane < 20) ? red[lane] : 0.f;
        t = warp_sum(t);
        if (lane == 0) red[0] = INV_TEMP / fmaxf(sqrtf(t), EPS);
    }
    __syncthreads();
    sp[tid] = p * red[0];
    __syncthreads();

    for (int q = wid; q < QUERY * WAY; q += 20) {
        const float* qr = inst + (size_t)(SHOT * WAY + q) * EMB;
        float dot = 0.f;
#pragma unroll
        for (int i = 0; i < 20; i++) {
            int d = lane + 32 * i;
            dot += qr[d] * sp[d];
        }
        dot = warp_sum(dot);
        if (lane == 0) out[q * WAY + w] = dot;
    }
}

// ---------------- launch ----------------------------------------------------
extern "C" void kernel_launch(void* const* d_in, const int* in_sizes, int n_in,
                              void* d_out, int out_size) {
    const float* inst = (const float*)d_in[0];   // [100, 640] fp32
    const float* mem  = (const float*)d_in[1];   // [100000, 640] fp32
    float* out = (float*)d_out;                  // [75, 5] fp32

    static int smem_set = 0;
    if (!smem_set) {
        cudaFuncSetAttribute(k2_memscan,
                             cudaFuncAttributeMaxDynamicSharedMemorySize, K2_SMEM);
        smem_set = 1;
    }

    k1_support<<<WAY, 256>>>(inst);

    // two no-op launches so k2 sits at ncu capture slot 3
    k_dummy<<<1, 32>>>();
    k_dummy<<<1, 32>>>();

    k2_memscan<<<K2_GRID, K2_THREADS, K2_SMEM>>>(mem);

    k3a_topk<<<WAY * SPLITS, K3A_THREADS>>>();
    k3b_proto_logits<<<WAY, 640>>>(inst, mem, out);
}